// round 15
// baseline (speedup 1.0000x reference)
#include <cuda_runtime.h>
#include <math.h>

#define BATCH 4
#define NPTS 8192
#define NROWS (BATCH*NPTS)
#define KNN 20
#define XC_STRIDE 224

// output layout (flattened tuple concat, f32)
#define OFF_VC  0
#define OFF_NV  768
#define OFF_NVS 772
#define OFF_GF  776
#define OFF_XC  1800

// ---------------- device scratch (no allocs allowed) ----------------
__device__ float g_norms[NROWS];
__device__ int   g_idx[NROWS*KNN];
__device__ unsigned long long g_part[(size_t)NROWS*4*(KNN+1)];  // per-part sorted key lists
__device__ __align__(16) float g_A [(size_t)NROWS*128];
__device__ __align__(16) float g_Bn[(size_t)NROWS*128];
__device__ float g_Wa[3][128*64];     // per-layer folded (Wc-Wn)*s
__device__ float g_Wb[3][128*64];     // per-layer folded Wn*s
__device__ float g_bias[3][128];      // per-layer folded bias
__device__ float g_Wgt[224*256];      // k-major (transposed) folded global weights
__device__ float g_bgf[256];
__device__ unsigned g_enc[BATCH*256];

__device__ __forceinline__ unsigned encf(float f){
  unsigned u = __float_as_uint(f);
  return (u & 0x80000000u) ? ~u : (u | 0x80000000u);
}
// inverse of encf
__device__ __forceinline__ float decf(unsigned e){
  unsigned u = (e & 0x80000000u) ? (e ^ 0x80000000u) : ~e;
  return __uint_as_float(u);
}

// packed f32x2 helpers
__device__ __forceinline__ void ffma2(unsigned long long &d, unsigned long long a, unsigned long long b){
  asm("fma.rn.f32x2 %0, %1, %2, %0;" : "+l"(d) : "l"(a), "l"(b));
}
__device__ __forceinline__ float hsum2(unsigned long long a){
  float lo, hi;
  asm("mov.b64 {%0, %1}, %2;" : "=f"(lo), "=f"(hi) : "l"(a));
  return lo + hi;
}
__device__ __forceinline__ unsigned long long pack2(float lo, float hi){
  unsigned long long r;
  asm("mov.b64 %0, {%1, %2};" : "=l"(r) : "f"(lo), "f"(hi));
  return r;
}

// ---------------- BN fold kernels ----------------
__global__ void fold_edge_kernel(const float* __restrict__ W, const float* __restrict__ ga,
                                 const float* __restrict__ be, const float* __restrict__ mu,
                                 const float* __restrict__ va, int O, int C, int layer) {
  int i = blockIdx.x*blockDim.x + threadIdx.x;
  if (i < O*C){
    int o = i / C, c = i - o*C;
    float s = ga[o]*rsqrtf(va[o]+1e-5f);
    float wc = W[o*2*C + c];
    float wn = W[o*2*C + C + c];
    g_Wa[layer][i] = (wc-wn)*s;
    g_Wb[layer][i] = wn*s;
  }
  if (i < O){
    float s = ga[i]*rsqrtf(va[i]+1e-5f);
    g_bias[layer][i] = be[i] - mu[i]*s;
  }
}

__global__ void fold_global_kernel(const float* __restrict__ Wg, const float* __restrict__ gg,
                                   const float* __restrict__ bg, const float* __restrict__ mg,
                                   const float* __restrict__ vg) {
  int i = blockIdx.x*blockDim.x + threadIdx.x;
  if (i < 224*256){
    int kk = i >> 8, o = i & 255;
    float s = gg[o]*rsqrtf(vg[o]+1e-5f);
    g_Wgt[i] = Wg[o*224+kk]*s;
  }
  if (i < 256){
    float s = gg[i]*rsqrtf(vg[i]+1e-5f);
    g_bgf[i] = bg[i] - mg[i]*s;
  }
  if (i < BATCH*256) g_enc[i] = 0u;  // encoded -inf
}

// ---------------- norms (vectorized when C%4==0) ----------------
template<int C>
__global__ void norms_kernel(const float* __restrict__ x, int stride) {
  int i = blockIdx.x*blockDim.x + threadIdx.x;
  if (i >= NROWS) return;
  const float* p = x + (size_t)i*stride;
  float s = 0.f;
  if constexpr (C % 4 == 0){
    #pragma unroll
    for (int c4 = 0; c4 < C/4; c4++){
      float4 v = __ldg(reinterpret_cast<const float4*>(p) + c4);
      s += v.x*v.x + v.y*v.y + v.z*v.z + v.w*v.w;
    }
  } else {
    #pragma unroll
    for (int c = 0; c < C; c++){ float v = p[c]; s += v*v; }
  }
  g_norms[i] = s;
}

// ---------------- exact kNN (candidate-split: blockIdx.z = part, HALVES parts) ----------------
// surrogate d = |c|^2 - 2<q,c> via dot(w, v): v = (c, |c|^2, 0pad) in smem tile,
// w = (-2q, 1, 0pad) packed f32x2 in registers.
// Each (block, part) scans NPTS/HALVES candidates; survivors pushed to per-lane
// smem buffer; sorted insertion deferred to drain points. G threads per query
// scan interleaved slices; in-smem G-merge. HALVES==1 writes g_idx directly
// (rank 0 = self dropped); HALVES>1 writes sorted key lists to g_part.
template<int C, int PC, int TS, int NTHR, int G, int OCC, int UF, int CAP, int HALVES>
__global__ void __launch_bounds__(NTHR, OCC) knn_kernel(const float* __restrict__ x, int stride) {
  constexpr int Q = NTHR / G;                 // queries per block
  constexpr int NPAIR = (C + 2) / 2;          // f32x2 pairs covering C channels + norm
  constexpr int SPAN = NPTS/HALVES;
  constexpr int TILE_B  = TS * PC * 4;
  constexpr int MERGE_B = (G > 1) ? NTHR * (KNN+1) * 8 : 0;
  constexpr int WORK_B  = (TILE_B > MERGE_B) ? TILE_B : MERGE_B;
  constexpr int SMEM_B  = WORK_B + NTHR * CAP * 8;
  __shared__ __align__(16) unsigned char sraw[SMEM_B];
  float* s = (float*)sraw;
  unsigned long long* sbuf = (unsigned long long*)(sraw + WORK_B);

  const int b  = blockIdx.y;
  const int half = blockIdx.z;
  const int cb = half*SPAN;                   // candidate base
  const int ql = threadIdx.x / G;             // local query
  const int g  = threadIdx.x % G;             // slice id
  const int qi = blockIdx.x*Q + ql;           // query point
  const size_t bbase = (size_t)b*NPTS;
  const float* qrow = x + (bbase + qi)*stride;

  // build packed query vector w = (-2q, 1, 0...)
  unsigned long long q2[NPAIR];
  {
    float wv[2*NPAIR];
    #pragma unroll
    for (int i = 0; i < 2*NPAIR; i++) wv[i] = 0.f;
    #pragma unroll
    for (int c = 0; c < C; c++) wv[c] = -2.f*qrow[c];
    wv[C] = 1.f;
    #pragma unroll
    for (int k = 0; k < NPAIR; k++) q2[k] = pack2(wv[2*k], wv[2*k+1]);
  }

  unsigned ek[KNN+1]; int ei[KNN+1];
  #pragma unroll
  for (int i = 0; i <= KNN; i++){ ek[i] = 0xFF7FFFFFu; ei[i] = 0x7FFFFFFF; }
  float worstd = 3.4e38f;
  int cnt = 0;

  for (int t0 = 0; t0 < SPAN; t0 += TS){
    __syncthreads();
    // ---- tile fill: PC floats per row = C channels + norm + zero pad ----
    if constexpr (C == 5){
      for (int i = threadIdx.x; i < TS*2; i += NTHR){
        int row = i >> 1, c4 = i & 1;
        const float* p = x + (bbase + cb + t0 + row)*stride;
        float4 v;
        if (c4 == 0) v = make_float4(p[0], p[1], p[2], p[3]);
        else         v = make_float4(p[4], g_norms[bbase + cb + t0 + row], 0.f, 0.f);
        reinterpret_cast<float4*>(s + row*PC)[c4] = v;
      }
    } else {
      constexpr int NV = TS*(PC/4);
      for (int i = threadIdx.x; i < NV; i += NTHR){
        int row = i/(PC/4), c4 = i - row*(PC/4);
        float4 v;
        if (c4 < C/4) v = *reinterpret_cast<const float4*>(x + (bbase + cb + t0 + row)*stride + 4*c4);
        else          v = make_float4(g_norms[bbase + cb + t0 + row], 0.f, 0.f, 0.f);
        reinterpret_cast<float4*>(s + row*PC)[c4] = v;
      }
    }
    __syncthreads();

    #pragma unroll 1
    for (int j0 = 0; j0 < TS; j0 += UF*G){
      float d[UF];
      #pragma unroll
      for (int u = 0; u < UF; u++){
        const int r = j0 + u*G + g;
        const ulonglong2* p = reinterpret_cast<const ulonglong2*>(s + r*PC);
        unsigned long long a0 = 0ull, a1 = 0ull;
        #pragma unroll
        for (int k = 0; k < NPAIR/2; k++){
          ulonglong2 v = p[k];
          ffma2(a0, q2[2*k],   v.x);
          ffma2(a1, q2[2*k+1], v.y);
        }
        if constexpr (NPAIR & 1){
          ffma2(a0, q2[NPAIR-1], reinterpret_cast<const unsigned long long*>(p)[NPAIR-1]);
        }
        d[u] = hsum2(a0) + hsum2(a1);
      }
      // cheap push of survivors (no sorted insert here)
      #pragma unroll
      for (int u = 0; u < UF; u++){
        float dd = d[u];
        int jj = cb + t0 + j0 + u*G + g;
        if (dd <= worstd){
          sbuf[cnt*NTHR + threadIdx.x] =
            ((unsigned long long)encf(dd) << 32) | (unsigned)jj;
          cnt++;
        }
      }
      // drain when any lane's buffer can't absorb another group
      if (__any_sync(0xFFFFFFFFu, cnt >= CAP-UF)){
        for (int i2 = 0; i2 < cnt; i2++){
          unsigned long long e = sbuf[i2*NTHR + threadIdx.x];
          unsigned kk = (unsigned)(e >> 32);
          if (kk < ek[KNN]){
            ek[KNN] = kk; ei[KNN] = (int)(unsigned)e;
            #pragma unroll
            for (int p2 = KNN; p2 >= 1; p2--){
              unsigned ta = ek[p2-1], tb = ek[p2];
              bool sw = tb < ta;
              ek[p2-1] = sw ? tb : ta;  ek[p2] = sw ? ta : tb;
              int ia = ei[p2-1], ib = ei[p2];
              ei[p2-1] = sw ? ib : ia;  ei[p2] = sw ? ia : ib;
            }
          }
        }
        cnt = 0;
        worstd = decf(ek[KNN]);
      }
    }
  }

  // final drain
  for (int i2 = 0; i2 < cnt; i2++){
    unsigned long long e = sbuf[i2*NTHR + threadIdx.x];
    unsigned kk = (unsigned)(e >> 32);
    if (kk < ek[KNN]){
      ek[KNN] = kk; ei[KNN] = (int)(unsigned)e;
      #pragma unroll
      for (int p2 = KNN; p2 >= 1; p2--){
        unsigned ta = ek[p2-1], tb = ek[p2];
        bool sw = tb < ta;
        ek[p2-1] = sw ? tb : ta;  ek[p2] = sw ? ta : tb;
        int ia = ei[p2-1], ib = ei[p2];
        ei[p2-1] = sw ? ib : ia;  ei[p2] = sw ? ia : ib;
      }
    }
  }

  if constexpr (G == 1){
    if constexpr (HALVES == 1){
      int* o = g_idx + (bbase + qi)*KNN;
      #pragma unroll
      for (int i = 1; i <= KNN; i++) o[i-1] = ei[i];
    } else {
      unsigned long long* op = g_part + ((bbase + qi)*HALVES + half)*(KNN+1);
      #pragma unroll
      for (int i = 0; i <= KNN; i++)
        op[i] = ((unsigned long long)ek[i] << 32) | (unsigned)ei[i];
    }
  } else {
    __syncthreads();
    unsigned* Ks = (unsigned*)sraw;
    int* Is = (int*)(sraw + sizeof(unsigned)*NTHR*(KNN+1));
    const int base = (ql*G + g)*(KNN+1);
    #pragma unroll
    for (int i = 0; i <= KNN; i++){ Ks[base+i] = ek[i]; Is[base+i] = ei[i]; }
    __syncthreads();
    if (g == 0){
      int hd[G];
      #pragma unroll
      for (int t = 0; t < G; t++) hd[t] = 0;
      int* o = g_idx + (bbase + qi)*KNN;
      unsigned long long* op = g_part + ((bbase + qi)*HALVES + half)*(KNN+1);
      for (int r = 0; r <= KNN; r++){
        unsigned bv = 0xFFFFFFFFu; int bidx = 0x7FFFFFFF, bt = 0;
        #pragma unroll
        for (int t = 0; t < G; t++){
          int h = hd[t];
          unsigned v = (h <= KNN) ? Ks[(ql*G+t)*(KNN+1)+h] : 0xFFFFFFFFu;
          int vi     = (h <= KNN) ? Is[(ql*G+t)*(KNN+1)+h] : 0x7FFFFFFF;
          if (v < bv || (v == bv && vi < bidx)){ bv = v; bidx = vi; bt = t; }
        }
        hd[bt]++;
        if constexpr (HALVES == 1){
          if (r > 0) o[r-1] = bidx;
        } else {
          op[r] = ((unsigned long long)bv << 32) | (unsigned)bidx;
        }
      }
    }
  }
}

// ---------------- global NPARTS-way merge of per-part top-21 lists ----------------
// Merge NPARTS sorted ascending key lists, take first KNN+1; rank 0 is self
// (minimal surrogate distance, tie-broken by index) and is dropped.
template<int NPARTS>
__global__ void knn_merge_kernel() {
  int q = blockIdx.x*256 + threadIdx.x;
  const unsigned long long* P = g_part + (size_t)q*NPARTS*(KNN+1);
  int* o = g_idx + (size_t)q*KNN;
  int hd[NPARTS];
  unsigned long long v[NPARTS];
  #pragma unroll
  for (int t = 0; t < NPARTS; t++){ hd[t] = 0; v[t] = __ldg(&P[t*(KNN+1)]); }
  #pragma unroll
  for (int r = 0; r <= KNN; r++){
    unsigned long long bv = 0xFFFFFFFFFFFFFFFFull; int bt = 0;
    #pragma unroll
    for (int t = 0; t < NPARTS; t++)
      if (v[t] < bv){ bv = v[t]; bt = t; }
    hd[bt]++;
    v[bt] = (hd[bt] <= KNN) ? __ldg(&P[bt*(KNN+1) + hd[bt]]) : 0xFFFFFFFFFFFFFFFFull;
    if (r > 0) o[r-1] = (int)(bv & 0xFFFFFFFFull);
  }
}

// ---------------- per-point transforms A = X*(Wc-Wn)^T + bias, Bn = X*Wn^T ----------------
template<int C, int O>
__global__ void __launch_bounds__(256) transform_kernel(const float* __restrict__ x, int stride, int layer) {
  __shared__ __align__(16) float sW[O*C];
  __shared__ float sb[O];
  const bool isA = (blockIdx.y == 0);
  const float* W = isA ? g_Wa[layer] : g_Wb[layer];
  for (int i = threadIdx.x; i < O*C; i += 256) sW[i] = W[i];
  for (int i = threadIdx.x; i < O;   i += 256) sb[i] = isA ? g_bias[layer][i] : 0.f;
  __syncthreads();
  int r = blockIdx.x*256 + threadIdx.x;
  float q[C];
  #pragma unroll
  for (int c = 0; c < C; c++) q[c] = x[(size_t)r*stride + c];
  float* dst = (isA ? g_A : g_Bn) + (size_t)r*O;
  #pragma unroll 4
  for (int o = 0; o < O; o++){
    float acc = sb[o];
    if (C % 4 == 0) {
      const float4* w4 = reinterpret_cast<const float4*>(sW + o*C);
      #pragma unroll
      for (int c4 = 0; c4 < C/4; c4++){
        float4 w = w4[c4];
        acc += q[4*c4+0]*w.x + q[4*c4+1]*w.y + q[4*c4+2]*w.z + q[4*c4+3]*w.w;
      }
    } else {
      #pragma unroll
      for (int c = 0; c < C; c++) acc += q[c]*sW[o*C+c];
    }
    dst[o] = acc;
  }
}

// ---------------- gather + max + leaky, write into x_concat ----------------
template<int O>
__global__ void __launch_bounds__(256) gathermax_kernel(float* __restrict__ outc) {
  const int TPP = O/4;            // threads per point (float4 lanes)
  const int PP  = 256/TPP;        // points per block
  int pl = threadIdx.x / TPP;
  int ol = threadIdx.x % TPP;
  int r  = blockIdx.x * PP + pl;  // global row
  int b  = r / NPTS;
  const int* id = g_idx + (size_t)r*KNN;
  const size_t brow = (size_t)b*NPTS;
  float4 mx = make_float4(-3.4e38f,-3.4e38f,-3.4e38f,-3.4e38f);
  #pragma unroll 5
  for (int j = 0; j < KNN; j++){
    int nb = id[j];
    const float4* Bp = reinterpret_cast<const float4*>(g_Bn + (brow + nb)*O);
    float4 v = __ldg(&Bp[ol]);
    mx.x = fmaxf(mx.x, v.x); mx.y = fmaxf(mx.y, v.y);
    mx.z = fmaxf(mx.z, v.z); mx.w = fmaxf(mx.w, v.w);
  }
  const float4* Ap = reinterpret_cast<const float4*>(g_A + (size_t)r*O);
  float4 a = Ap[ol];
  float4 y;
  y.x = a.x + mx.x; y.x = y.x >= 0.f ? y.x : 0.2f*y.x;
  y.y = a.y + mx.y; y.y = y.y >= 0.f ? y.y : 0.2f*y.y;
  y.z = a.z + mx.z; y.z = y.z >= 0.f ? y.z : 0.2f*y.z;
  y.w = a.w + mx.w; y.w = y.w >= 0.f ? y.w : 0.2f*y.w;
  *reinterpret_cast<float4*>(outc + (size_t)r*XC_STRIDE + ol*4) = y;
}

// ---------------- global conv (224 -> 256) + per-batch max ----------------
__global__ void __launch_bounds__(256) globalconv_kernel(const float* __restrict__ xc) {
  __shared__ float Xs[64][33];
  __shared__ __align__(16) float Ws[32][64];
  __shared__ unsigned smax[64];
  const int b = blockIdx.y, n0 = blockIdx.x*64, ob = blockIdx.z*64;
  const int rr = threadIdx.x >> 2, oc = threadIdx.x & 3;
  float acc[16];
  #pragma unroll
  for (int i = 0; i < 16; i++) acc[i] = g_bgf[ob + oc*16 + i];

  for (int kc = 0; kc < 224; kc += 32){
    __syncthreads();
    for (int i = threadIdx.x; i < 64*32; i += 256){
      int r2 = i >> 5, kk = i & 31;
      Xs[r2][kk] = xc[((size_t)b*NPTS + n0 + r2)*XC_STRIDE + kc + kk];
    }
    for (int i = threadIdx.x; i < 32*64; i += 256){
      int kk = i >> 6, oo = i & 63;
      Ws[kk][oo] = g_Wgt[(kc+kk)*256 + ob + oo];
    }
    __syncthreads();
    #pragma unroll
    for (int kk = 0; kk < 32; kk++){
      float xv = Xs[rr][kk];
      const float4* w4 = reinterpret_cast<const float4*>(&Ws[kk][oc*16]);
      #pragma unroll
      for (int q4 = 0; q4 < 4; q4++){
        float4 w = w4[q4];
        acc[q4*4+0] += xv*w.x; acc[q4*4+1] += xv*w.y;
        acc[q4*4+2] += xv*w.z; acc[q4*4+3] += xv*w.w;
      }
    }
  }
  if (threadIdx.x < 64) smax[threadIdx.x] = 0u;
  __syncthreads();
  #pragma unroll
  for (int i = 0; i < 16; i++){
    float y = acc[i]; y = y >= 0.f ? y : 0.2f*y;
    atomicMax(&smax[oc*16 + i], encf(y));
  }
  __syncthreads();
  if (threadIdx.x < 64) atomicMax(&g_enc[b*256 + ob + threadIdx.x], smax[threadIdx.x]);
}

// ---------------- heads ----------------
__global__ void head_kernel(const float* __restrict__ Wv1, const float* __restrict__ bv1,
                            const float* __restrict__ Wv2, const float* __restrict__ bv2,
                            const float* __restrict__ Wq1, const float* __restrict__ bq1,
                            const float* __restrict__ Wq2, const float* __restrict__ bq2,
                            float* __restrict__ out) {
  __shared__ float gf[256]; __shared__ float h[512]; __shared__ float qh[64];
  int tid = threadIdx.x;
  for (int b = 0; b < BATCH; b++){
    {
      float v = decf(g_enc[b*256 + tid]);
      gf[tid] = v;
      out[OFF_GF + b*256 + tid] = v;
    }
    __syncthreads();
    for (int o = tid; o < 512; o += 256){
      float a = bv1[o];
      for (int c = 0; c < 256; c++) a += gf[c]*Wv1[o*256+c];
      h[o] = fmaxf(a, 0.f);
    }
    if (tid < 64){
      float a = bq1[tid];
      for (int c = 0; c < 256; c++) a += gf[c]*Wq1[tid*256+c];
      qh[tid] = fmaxf(a, 0.f);
    }
    __syncthreads();
    if (tid < 192){
      float a = bv2[tid];
      for (int c = 0; c < 512; c++) a += h[c]*Wv2[tid*512+c];
      out[OFF_VC + b*192 + tid] = a;
    }
    if (tid == 0){
      float a = bq2[0];
      for (int c = 0; c < 64; c++) a += qh[c]*Wq2[c];
      float s = 1.f/(1.f + expf(-a));
      out[OFF_NVS + b] = s;
      float nv = rintf(s*64.f);
      nv = fminf(fmaxf(nv, 1.f), 64.f);
      out[OFF_NV + b] = nv;
    }
    __syncthreads();
  }
}

// ---------------- launch ----------------
extern "C" void kernel_launch(void* const* d_in, const int* in_sizes, int n_in,
                              void* d_out, int out_size) {
  const float* x   = (const float*)d_in[0];
  const float* W1  = (const float*)d_in[1];
  const float* g1  = (const float*)d_in[2];
  const float* b1  = (const float*)d_in[3];
  const float* m1  = (const float*)d_in[4];
  const float* v1  = (const float*)d_in[5];
  const float* W2  = (const float*)d_in[6];
  const float* g2  = (const float*)d_in[7];
  const float* b2  = (const float*)d_in[8];
  const float* m2  = (const float*)d_in[9];
  const float* v2  = (const float*)d_in[10];
  const float* W3  = (const float*)d_in[11];
  const float* g3  = (const float*)d_in[12];
  const float* b3  = (const float*)d_in[13];
  const float* m3  = (const float*)d_in[14];
  const float* v3  = (const float*)d_in[15];
  const float* Wg  = (const float*)d_in[16];
  const float* gg  = (const float*)d_in[17];
  const float* bg  = (const float*)d_in[18];
  const float* mg  = (const float*)d_in[19];
  const float* vg  = (const float*)d_in[20];
  const float* Wv1 = (const float*)d_in[21];
  const float* bv1 = (const float*)d_in[22];
  const float* Wv2 = (const float*)d_in[23];
  const float* bv2 = (const float*)d_in[24];
  const float* Wq1 = (const float*)d_in[25];
  const float* bq1 = (const float*)d_in[26];
  const float* Wq2 = (const float*)d_in[27];
  const float* bq2 = (const float*)d_in[28];

  float* out = (float*)d_out;
  float* xc  = out + OFF_XC;

  norms_kernel<5><<<NROWS/256, 256>>>(x, 5);                                   // 1
  fold_edge_kernel<<<(32*5+255)/256, 256>>>(W1, g1, b1, m1, v1, 32, 5, 0);     // 2
  fold_edge_kernel<<<(64*32+255)/256, 256>>>(W2, g2, b2, m2, v2, 64, 32, 1);   // 3

  // ---- EdgeConv 1: 5 -> 32 (cols 0..31) ---- (knn at launch #4 for ncu window)
  knn_kernel<5,8,256,128,2,3,8,12,1><<<dim3(NPTS/64, BATCH), 128>>>(x, 5);     // 4
  fold_edge_kernel<<<(128*64+255)/256, 256>>>(W3, g3, b3, m3, v3, 128, 64, 2);
  fold_global_kernel<<<224, 256>>>(Wg, gg, bg, mg, vg);
  transform_kernel<5,32><<<dim3(NROWS/256, 2), 256>>>(x, 5, 0);
  gathermax_kernel<32><<<NROWS/32, 256>>>(xc + 0);

  // ---- EdgeConv 2: 32 -> 64 (cols 32..95) ----
  norms_kernel<32><<<NROWS/256, 256>>>(xc, XC_STRIDE);
  knn_kernel<32,36,256,128,2,3,4,8,2><<<dim3(NPTS/64, BATCH, 2), 128>>>(xc, XC_STRIDE);
  knn_merge_kernel<2><<<NROWS/256, 256>>>();
  transform_kernel<32,64><<<dim3(NROWS/256, 2), 256>>>(xc, XC_STRIDE, 1);
  gathermax_kernel<64><<<NROWS/16, 256>>>(xc + 32);

  // ---- EdgeConv 3: 64 -> 128 (cols 96..223) ----
  norms_kernel<64><<<NROWS/256, 256>>>(xc + 32, XC_STRIDE);
  knn_kernel<64,68,128,128,2,3,4,8,4><<<dim3(NPTS/64, BATCH, 4), 128>>>(xc + 32, XC_STRIDE);
  knn_merge_kernel<4><<<NROWS/256, 256>>>();
  transform_kernel<64,128><<<dim3(NROWS/256, 2), 256>>>(xc + 32, XC_STRIDE, 2);
  gathermax_kernel<128><<<NROWS/8, 256>>>(xc + 96);

  // ---- global conv + maxpool + heads ----
  globalconv_kernel<<<dim3(NPTS/64, BATCH, 4), 256>>>(xc);
  head_kernel<<<1, 256>>>(Wv1, bv1, Wv2, bv2, Wq1, bq1, Wq2, bq2, out);
}

// round 16
// speedup vs baseline: 1.0200x; 1.0200x over previous
#include <cuda_runtime.h>
#include <math.h>

#define BATCH 4
#define NPTS 8192
#define NROWS (BATCH*NPTS)
#define KNN 20
#define XC_STRIDE 224

// output layout (flattened tuple concat, f32)
#define OFF_VC  0
#define OFF_NV  768
#define OFF_NVS 772
#define OFF_GF  776
#define OFF_XC  1800

// ---------------- device scratch (no allocs allowed) ----------------
__device__ float g_norms[NROWS];
__device__ int   g_idx[NROWS*KNN];
__device__ unsigned long long g_part[(size_t)NROWS*4*(KNN+1)];  // per-part sorted key lists
__device__ __align__(16) float g_A [(size_t)NROWS*128];
__device__ __align__(16) float g_Bn[(size_t)NROWS*128];
__device__ float g_Wa[3][128*64];     // per-layer folded (Wc-Wn)*s
__device__ float g_Wb[3][128*64];     // per-layer folded Wn*s
__device__ float g_bias[3][128];      // per-layer folded bias
__device__ float g_Wgt[224*256];      // k-major (transposed) folded global weights
__device__ float g_bgf[256];
__device__ unsigned g_enc[BATCH*256];

__device__ __forceinline__ unsigned encf(float f){
  unsigned u = __float_as_uint(f);
  return (u & 0x80000000u) ? ~u : (u | 0x80000000u);
}
// inverse of encf
__device__ __forceinline__ float decf(unsigned e){
  unsigned u = (e & 0x80000000u) ? (e ^ 0x80000000u) : ~e;
  return __uint_as_float(u);
}

// packed f32x2 helpers
__device__ __forceinline__ void ffma2(unsigned long long &d, unsigned long long a, unsigned long long b){
  asm("fma.rn.f32x2 %0, %1, %2, %0;" : "+l"(d) : "l"(a), "l"(b));
}
__device__ __forceinline__ float hsum2(unsigned long long a){
  float lo, hi;
  asm("mov.b64 {%0, %1}, %2;" : "=f"(lo), "=f"(hi) : "l"(a));
  return lo + hi;
}
__device__ __forceinline__ unsigned long long pack2(float lo, float hi){
  unsigned long long r;
  asm("mov.b64 %0, {%1, %2};" : "=l"(r) : "f"(lo), "f"(hi));
  return r;
}

// ---------------- BN fold kernels ----------------
__global__ void fold_edge_kernel(const float* __restrict__ W, const float* __restrict__ ga,
                                 const float* __restrict__ be, const float* __restrict__ mu,
                                 const float* __restrict__ va, int O, int C, int layer) {
  int i = blockIdx.x*blockDim.x + threadIdx.x;
  if (i < O*C){
    int o = i / C, c = i - o*C;
    float s = ga[o]*rsqrtf(va[o]+1e-5f);
    float wc = W[o*2*C + c];
    float wn = W[o*2*C + C + c];
    g_Wa[layer][i] = (wc-wn)*s;
    g_Wb[layer][i] = wn*s;
  }
  if (i < O){
    float s = ga[i]*rsqrtf(va[i]+1e-5f);
    g_bias[layer][i] = be[i] - mu[i]*s;
  }
}

__global__ void fold_global_kernel(const float* __restrict__ Wg, const float* __restrict__ gg,
                                   const float* __restrict__ bg, const float* __restrict__ mg,
                                   const float* __restrict__ vg) {
  int i = blockIdx.x*blockDim.x + threadIdx.x;
  if (i < 224*256){
    int kk = i >> 8, o = i & 255;
    float s = gg[o]*rsqrtf(vg[o]+1e-5f);
    g_Wgt[i] = Wg[o*224+kk]*s;
  }
  if (i < 256){
    float s = gg[i]*rsqrtf(vg[i]+1e-5f);
    g_bgf[i] = bg[i] - mg[i]*s;
  }
  if (i < BATCH*256) g_enc[i] = 0u;  // encoded -inf
}

// ---------------- norms (vectorized when C%4==0) ----------------
template<int C>
__global__ void norms_kernel(const float* __restrict__ x, int stride) {
  int i = blockIdx.x*blockDim.x + threadIdx.x;
  if (i >= NROWS) return;
  const float* p = x + (size_t)i*stride;
  float s = 0.f;
  if constexpr (C % 4 == 0){
    #pragma unroll
    for (int c4 = 0; c4 < C/4; c4++){
      float4 v = __ldg(reinterpret_cast<const float4*>(p) + c4);
      s += v.x*v.x + v.y*v.y + v.z*v.z + v.w*v.w;
    }
  } else {
    #pragma unroll
    for (int c = 0; c < C; c++){ float v = p[c]; s += v*v; }
  }
  g_norms[i] = s;
}

// ---------------- exact kNN (candidate-split: blockIdx.z = part, HALVES parts) ----------------
// surrogate d = |c|^2 - 2<q,c> via dot(w, v): v = (c, |c|^2, 0pad) in smem tile,
// w = (-2q, 1, 0pad) packed f32x2 in registers.
// Each (block, part) scans NPTS/HALVES candidates; survivors pushed to per-lane
// smem buffer; sorted insertion deferred to drain points. G threads per query
// scan interleaved slices; in-smem G-merge. HALVES==1 writes g_idx directly
// (rank 0 = self dropped); HALVES>1 writes sorted key lists to g_part.
template<int C, int PC, int TS, int NTHR, int G, int OCC, int UF, int CAP, int HALVES>
__global__ void __launch_bounds__(NTHR, OCC) knn_kernel(const float* __restrict__ x, int stride) {
  constexpr int Q = NTHR / G;                 // queries per block
  constexpr int NPAIR = (C + 2) / 2;          // f32x2 pairs covering C channels + norm
  constexpr int SPAN = NPTS/HALVES;
  constexpr int TILE_B  = TS * PC * 4;
  constexpr int MERGE_B = (G > 1) ? NTHR * (KNN+1) * 8 : 0;
  constexpr int WORK_B  = (TILE_B > MERGE_B) ? TILE_B : MERGE_B;
  constexpr int SMEM_B  = WORK_B + NTHR * CAP * 8;
  __shared__ __align__(16) unsigned char sraw[SMEM_B];
  float* s = (float*)sraw;
  unsigned long long* sbuf = (unsigned long long*)(sraw + WORK_B);

  const int b  = blockIdx.y;
  const int half = blockIdx.z;
  const int cb = half*SPAN;                   // candidate base
  const int ql = threadIdx.x / G;             // local query
  const int g  = threadIdx.x % G;             // slice id
  const int qi = blockIdx.x*Q + ql;           // query point
  const size_t bbase = (size_t)b*NPTS;
  const float* qrow = x + (bbase + qi)*stride;

  // build packed query vector w = (-2q, 1, 0...)
  unsigned long long q2[NPAIR];
  {
    float wv[2*NPAIR];
    #pragma unroll
    for (int i = 0; i < 2*NPAIR; i++) wv[i] = 0.f;
    #pragma unroll
    for (int c = 0; c < C; c++) wv[c] = -2.f*qrow[c];
    wv[C] = 1.f;
    #pragma unroll
    for (int k = 0; k < NPAIR; k++) q2[k] = pack2(wv[2*k], wv[2*k+1]);
  }

  unsigned ek[KNN+1]; int ei[KNN+1];
  #pragma unroll
  for (int i = 0; i <= KNN; i++){ ek[i] = 0xFF7FFFFFu; ei[i] = 0x7FFFFFFF; }
  float worstd = 3.4e38f;
  int cnt = 0;

  for (int t0 = 0; t0 < SPAN; t0 += TS){
    __syncthreads();
    // ---- tile fill: PC floats per row = C channels + norm + zero pad ----
    if constexpr (C == 5){
      for (int i = threadIdx.x; i < TS*2; i += NTHR){
        int row = i >> 1, c4 = i & 1;
        const float* p = x + (bbase + cb + t0 + row)*stride;
        float4 v;
        if (c4 == 0) v = make_float4(p[0], p[1], p[2], p[3]);
        else         v = make_float4(p[4], g_norms[bbase + cb + t0 + row], 0.f, 0.f);
        reinterpret_cast<float4*>(s + row*PC)[c4] = v;
      }
    } else {
      constexpr int NV = TS*(PC/4);
      for (int i = threadIdx.x; i < NV; i += NTHR){
        int row = i/(PC/4), c4 = i - row*(PC/4);
        float4 v;
        if (c4 < C/4) v = *reinterpret_cast<const float4*>(x + (bbase + cb + t0 + row)*stride + 4*c4);
        else          v = make_float4(g_norms[bbase + cb + t0 + row], 0.f, 0.f, 0.f);
        reinterpret_cast<float4*>(s + row*PC)[c4] = v;
      }
    }
    __syncthreads();

    #pragma unroll 1
    for (int j0 = 0; j0 < TS; j0 += UF*G){
      float d[UF];
      #pragma unroll
      for (int u = 0; u < UF; u++){
        const int r = j0 + u*G + g;
        const ulonglong2* p = reinterpret_cast<const ulonglong2*>(s + r*PC);
        unsigned long long a0 = 0ull, a1 = 0ull;
        #pragma unroll
        for (int k = 0; k < NPAIR/2; k++){
          ulonglong2 v = p[k];
          ffma2(a0, q2[2*k],   v.x);
          ffma2(a1, q2[2*k+1], v.y);
        }
        if constexpr (NPAIR & 1){
          ffma2(a0, q2[NPAIR-1], reinterpret_cast<const unsigned long long*>(p)[NPAIR-1]);
        }
        d[u] = hsum2(a0) + hsum2(a1);
      }
      // cheap push of survivors (no sorted insert here)
      #pragma unroll
      for (int u = 0; u < UF; u++){
        float dd = d[u];
        int jj = cb + t0 + j0 + u*G + g;
        if (dd <= worstd){
          sbuf[cnt*NTHR + threadIdx.x] =
            ((unsigned long long)encf(dd) << 32) | (unsigned)jj;
          cnt++;
        }
      }
      // drain when any lane's buffer can't absorb another group
      if (__any_sync(0xFFFFFFFFu, cnt >= CAP-UF)){
        for (int i2 = 0; i2 < cnt; i2++){
          unsigned long long e = sbuf[i2*NTHR + threadIdx.x];
          unsigned kk = (unsigned)(e >> 32);
          if (kk < ek[KNN]){
            ek[KNN] = kk; ei[KNN] = (int)(unsigned)e;
            #pragma unroll
            for (int p2 = KNN; p2 >= 1; p2--){
              unsigned ta = ek[p2-1], tb = ek[p2];
              bool sw = tb < ta;
              ek[p2-1] = sw ? tb : ta;  ek[p2] = sw ? ta : tb;
              int ia = ei[p2-1], ib = ei[p2];
              ei[p2-1] = sw ? ib : ia;  ei[p2] = sw ? ia : ib;
            }
          }
        }
        cnt = 0;
        worstd = decf(ek[KNN]);
      }
    }
  }

  // final drain
  for (int i2 = 0; i2 < cnt; i2++){
    unsigned long long e = sbuf[i2*NTHR + threadIdx.x];
    unsigned kk = (unsigned)(e >> 32);
    if (kk < ek[KNN]){
      ek[KNN] = kk; ei[KNN] = (int)(unsigned)e;
      #pragma unroll
      for (int p2 = KNN; p2 >= 1; p2--){
        unsigned ta = ek[p2-1], tb = ek[p2];
        bool sw = tb < ta;
        ek[p2-1] = sw ? tb : ta;  ek[p2] = sw ? ta : tb;
        int ia = ei[p2-1], ib = ei[p2];
        ei[p2-1] = sw ? ib : ia;  ei[p2] = sw ? ia : ib;
      }
    }
  }

  if constexpr (G == 1){
    if constexpr (HALVES == 1){
      int* o = g_idx + (bbase + qi)*KNN;
      #pragma unroll
      for (int i = 1; i <= KNN; i++) o[i-1] = ei[i];
    } else {
      unsigned long long* op = g_part + ((bbase + qi)*HALVES + half)*(KNN+1);
      #pragma unroll
      for (int i = 0; i <= KNN; i++)
        op[i] = ((unsigned long long)ek[i] << 32) | (unsigned)ei[i];
    }
  } else {
    __syncthreads();
    unsigned* Ks = (unsigned*)sraw;
    int* Is = (int*)(sraw + sizeof(unsigned)*NTHR*(KNN+1));
    const int base = (ql*G + g)*(KNN+1);
    #pragma unroll
    for (int i = 0; i <= KNN; i++){ Ks[base+i] = ek[i]; Is[base+i] = ei[i]; }
    __syncthreads();
    if (g == 0){
      int hd[G];
      #pragma unroll
      for (int t = 0; t < G; t++) hd[t] = 0;
      int* o = g_idx + (bbase + qi)*KNN;
      unsigned long long* op = g_part + ((bbase + qi)*HALVES + half)*(KNN+1);
      for (int r = 0; r <= KNN; r++){
        unsigned bv = 0xFFFFFFFFu; int bidx = 0x7FFFFFFF, bt = 0;
        #pragma unroll
        for (int t = 0; t < G; t++){
          int h = hd[t];
          unsigned v = (h <= KNN) ? Ks[(ql*G+t)*(KNN+1)+h] : 0xFFFFFFFFu;
          int vi     = (h <= KNN) ? Is[(ql*G+t)*(KNN+1)+h] : 0x7FFFFFFF;
          if (v < bv || (v == bv && vi < bidx)){ bv = v; bidx = vi; bt = t; }
        }
        hd[bt]++;
        if constexpr (HALVES == 1){
          if (r > 0) o[r-1] = bidx;
        } else {
          op[r] = ((unsigned long long)bv << 32) | (unsigned)bidx;
        }
      }
    }
  }
}

// ---------------- global NPARTS-way merge of per-part top-21 lists ----------------
// Merge NPARTS sorted ascending key lists, take first KNN+1; rank 0 is self
// (minimal surrogate distance, tie-broken by index) and is dropped.
template<int NPARTS>
__global__ void knn_merge_kernel() {
  int q = blockIdx.x*256 + threadIdx.x;
  const unsigned long long* P = g_part + (size_t)q*NPARTS*(KNN+1);
  int* o = g_idx + (size_t)q*KNN;
  int hd[NPARTS];
  unsigned long long v[NPARTS];
  #pragma unroll
  for (int t = 0; t < NPARTS; t++){ hd[t] = 0; v[t] = __ldg(&P[t*(KNN+1)]); }
  #pragma unroll
  for (int r = 0; r <= KNN; r++){
    unsigned long long bv = 0xFFFFFFFFFFFFFFFFull; int bt = 0;
    #pragma unroll
    for (int t = 0; t < NPARTS; t++)
      if (v[t] < bv){ bv = v[t]; bt = t; }
    hd[bt]++;
    v[bt] = (hd[bt] <= KNN) ? __ldg(&P[bt*(KNN+1) + hd[bt]]) : 0xFFFFFFFFFFFFFFFFull;
    if (r > 0) o[r-1] = (int)(bv & 0xFFFFFFFFull);
  }
}

// ---------------- per-point transforms A = X*(Wc-Wn)^T + bias, Bn = X*Wn^T ----------------
template<int C, int O>
__global__ void __launch_bounds__(256) transform_kernel(const float* __restrict__ x, int stride, int layer) {
  __shared__ __align__(16) float sW[O*C];
  __shared__ float sb[O];
  const bool isA = (blockIdx.y == 0);
  const float* W = isA ? g_Wa[layer] : g_Wb[layer];
  for (int i = threadIdx.x; i < O*C; i += 256) sW[i] = W[i];
  for (int i = threadIdx.x; i < O;   i += 256) sb[i] = isA ? g_bias[layer][i] : 0.f;
  __syncthreads();
  int r = blockIdx.x*256 + threadIdx.x;
  float q[C];
  #pragma unroll
  for (int c = 0; c < C; c++) q[c] = x[(size_t)r*stride + c];
  float* dst = (isA ? g_A : g_Bn) + (size_t)r*O;
  #pragma unroll 4
  for (int o = 0; o < O; o++){
    float acc = sb[o];
    if (C % 4 == 0) {
      const float4* w4 = reinterpret_cast<const float4*>(sW + o*C);
      #pragma unroll
      for (int c4 = 0; c4 < C/4; c4++){
        float4 w = w4[c4];
        acc += q[4*c4+0]*w.x + q[4*c4+1]*w.y + q[4*c4+2]*w.z + q[4*c4+3]*w.w;
      }
    } else {
      #pragma unroll
      for (int c = 0; c < C; c++) acc += q[c]*sW[o*C+c];
    }
    dst[o] = acc;
  }
}

// ---------------- gather + max + leaky, write into x_concat ----------------
template<int O>
__global__ void __launch_bounds__(256) gathermax_kernel(float* __restrict__ outc) {
  const int TPP = O/4;            // threads per point (float4 lanes)
  const int PP  = 256/TPP;        // points per block
  int pl = threadIdx.x / TPP;
  int ol = threadIdx.x % TPP;
  int r  = blockIdx.x * PP + pl;  // global row
  int b  = r / NPTS;
  const int* id = g_idx + (size_t)r*KNN;
  const size_t brow = (size_t)b*NPTS;
  float4 mx = make_float4(-3.4e38f,-3.4e38f,-3.4e38f,-3.4e38f);
  #pragma unroll 5
  for (int j = 0; j < KNN; j++){
    int nb = id[j];
    const float4* Bp = reinterpret_cast<const float4*>(g_Bn + (brow + nb)*O);
    float4 v = __ldg(&Bp[ol]);
    mx.x = fmaxf(mx.x, v.x); mx.y = fmaxf(mx.y, v.y);
    mx.z = fmaxf(mx.z, v.z); mx.w = fmaxf(mx.w, v.w);
  }
  const float4* Ap = reinterpret_cast<const float4*>(g_A + (size_t)r*O);
  float4 a = Ap[ol];
  float4 y;
  y.x = a.x + mx.x; y.x = y.x >= 0.f ? y.x : 0.2f*y.x;
  y.y = a.y + mx.y; y.y = y.y >= 0.f ? y.y : 0.2f*y.y;
  y.z = a.z + mx.z; y.z = y.z >= 0.f ? y.z : 0.2f*y.z;
  y.w = a.w + mx.w; y.w = y.w >= 0.f ? y.w : 0.2f*y.w;
  *reinterpret_cast<float4*>(outc + (size_t)r*XC_STRIDE + ol*4) = y;
}

// ---------------- global conv (224 -> 256) + per-batch max ----------------
__global__ void __launch_bounds__(256) globalconv_kernel(const float* __restrict__ xc) {
  __shared__ float Xs[64][33];
  __shared__ __align__(16) float Ws[32][64];
  __shared__ unsigned smax[64];
  const int b = blockIdx.y, n0 = blockIdx.x*64, ob = blockIdx.z*64;
  const int rr = threadIdx.x >> 2, oc = threadIdx.x & 3;
  float acc[16];
  #pragma unroll
  for (int i = 0; i < 16; i++) acc[i] = g_bgf[ob + oc*16 + i];

  for (int kc = 0; kc < 224; kc += 32){
    __syncthreads();
    for (int i = threadIdx.x; i < 64*32; i += 256){
      int r2 = i >> 5, kk = i & 31;
      Xs[r2][kk] = xc[((size_t)b*NPTS + n0 + r2)*XC_STRIDE + kc + kk];
    }
    for (int i = threadIdx.x; i < 32*64; i += 256){
      int kk = i >> 6, oo = i & 63;
      Ws[kk][oo] = g_Wgt[(kc+kk)*256 + ob + oo];
    }
    __syncthreads();
    #pragma unroll
    for (int kk = 0; kk < 32; kk++){
      float xv = Xs[rr][kk];
      const float4* w4 = reinterpret_cast<const float4*>(&Ws[kk][oc*16]);
      #pragma unroll
      for (int q4 = 0; q4 < 4; q4++){
        float4 w = w4[q4];
        acc[q4*4+0] += xv*w.x; acc[q4*4+1] += xv*w.y;
        acc[q4*4+2] += xv*w.z; acc[q4*4+3] += xv*w.w;
      }
    }
  }
  if (threadIdx.x < 64) smax[threadIdx.x] = 0u;
  __syncthreads();
  #pragma unroll
  for (int i = 0; i < 16; i++){
    float y = acc[i]; y = y >= 0.f ? y : 0.2f*y;
    atomicMax(&smax[oc*16 + i], encf(y));
  }
  __syncthreads();
  if (threadIdx.x < 64) atomicMax(&g_enc[b*256 + ob + threadIdx.x], smax[threadIdx.x]);
}

// ---------------- heads ----------------
__global__ void head_kernel(const float* __restrict__ Wv1, const float* __restrict__ bv1,
                            const float* __restrict__ Wv2, const float* __restrict__ bv2,
                            const float* __restrict__ Wq1, const float* __restrict__ bq1,
                            const float* __restrict__ Wq2, const float* __restrict__ bq2,
                            float* __restrict__ out) {
  __shared__ float gf[256]; __shared__ float h[512]; __shared__ float qh[64];
  int tid = threadIdx.x;
  for (int b = 0; b < BATCH; b++){
    {
      float v = decf(g_enc[b*256 + tid]);
      gf[tid] = v;
      out[OFF_GF + b*256 + tid] = v;
    }
    __syncthreads();
    for (int o = tid; o < 512; o += 256){
      float a = bv1[o];
      for (int c = 0; c < 256; c++) a += gf[c]*Wv1[o*256+c];
      h[o] = fmaxf(a, 0.f);
    }
    if (tid < 64){
      float a = bq1[tid];
      for (int c = 0; c < 256; c++) a += gf[c]*Wq1[tid*256+c];
      qh[tid] = fmaxf(a, 0.f);
    }
    __syncthreads();
    if (tid < 192){
      float a = bv2[tid];
      for (int c = 0; c < 512; c++) a += h[c]*Wv2[tid*512+c];
      out[OFF_VC + b*192 + tid] = a;
    }
    if (tid == 0){
      float a = bq2[0];
      for (int c = 0; c < 64; c++) a += qh[c]*Wq2[c];
      float s = 1.f/(1.f + expf(-a));
      out[OFF_NVS + b] = s;
      float nv = rintf(s*64.f);
      nv = fminf(fmaxf(nv, 1.f), 64.f);
      out[OFF_NV + b] = nv;
    }
    __syncthreads();
  }
}

// ---------------- launch ----------------
extern "C" void kernel_launch(void* const* d_in, const int* in_sizes, int n_in,
                              void* d_out, int out_size) {
  const float* x   = (const float*)d_in[0];
  const float* W1  = (const float*)d_in[1];
  const float* g1  = (const float*)d_in[2];
  const float* b1  = (const float*)d_in[3];
  const float* m1  = (const float*)d_in[4];
  const float* v1  = (const float*)d_in[5];
  const float* W2  = (const float*)d_in[6];
  const float* g2  = (const float*)d_in[7];
  const float* b2  = (const float*)d_in[8];
  const float* m2  = (const float*)d_in[9];
  const float* v2  = (const float*)d_in[10];
  const float* W3  = (const float*)d_in[11];
  const float* g3  = (const float*)d_in[12];
  const float* b3  = (const float*)d_in[13];
  const float* m3  = (const float*)d_in[14];
  const float* v3  = (const float*)d_in[15];
  const float* Wg  = (const float*)d_in[16];
  const float* gg  = (const float*)d_in[17];
  const float* bg  = (const float*)d_in[18];
  const float* mg  = (const float*)d_in[19];
  const float* vg  = (const float*)d_in[20];
  const float* Wv1 = (const float*)d_in[21];
  const float* bv1 = (const float*)d_in[22];
  const float* Wv2 = (const float*)d_in[23];
  const float* bv2 = (const float*)d_in[24];
  const float* Wq1 = (const float*)d_in[25];
  const float* bq1 = (const float*)d_in[26];
  const float* Wq2 = (const float*)d_in[27];
  const float* bq2 = (const float*)d_in[28];

  float* out = (float*)d_out;
  float* xc  = out + OFF_XC;

  norms_kernel<5><<<NROWS/256, 256>>>(x, 5);                                   // 1
  fold_edge_kernel<<<(32*5+255)/256, 256>>>(W1, g1, b1, m1, v1, 32, 5, 0);     // 2
  fold_edge_kernel<<<(64*32+255)/256, 256>>>(W2, g2, b2, m2, v2, 64, 32, 1);   // 3

  // ---- EdgeConv 1: 5 -> 32 (cols 0..31) ---- (knn at launch #4 for ncu window)
  knn_kernel<5,8,256,128,2,3,8,12,1><<<dim3(NPTS/64, BATCH), 128>>>(x, 5);     // 4
  fold_edge_kernel<<<(128*64+255)/256, 256>>>(W3, g3, b3, m3, v3, 128, 64, 2);
  fold_global_kernel<<<224, 256>>>(Wg, gg, bg, mg, vg);
  transform_kernel<5,32><<<dim3(NROWS/256, 2), 256>>>(x, 5, 0);
  gathermax_kernel<32><<<NROWS/32, 256>>>(xc + 0);

  // ---- EdgeConv 2: 32 -> 64 (cols 32..95) ----
  norms_kernel<32><<<NROWS/256, 256>>>(xc, XC_STRIDE);
  knn_kernel<32,36,256,128,2,3,4,8,2><<<dim3(NPTS/64, BATCH, 2), 128>>>(xc, XC_STRIDE);
  knn_merge_kernel<2><<<NROWS/256, 256>>>();
  transform_kernel<32,64><<<dim3(NROWS/256, 2), 256>>>(xc, XC_STRIDE, 1);
  gathermax_kernel<64><<<NROWS/16, 256>>>(xc + 32);

  // ---- EdgeConv 3: 64 -> 128 (cols 96..223) ----
  norms_kernel<64><<<NROWS/256, 256>>>(xc + 32, XC_STRIDE);
  knn_kernel<64,68,128,128,2,3,4,8,2><<<dim3(NPTS/64, BATCH, 2), 128>>>(xc + 32, XC_STRIDE);
  knn_merge_kernel<2><<<NROWS/256, 256>>>();
  transform_kernel<64,128><<<dim3(NROWS/256, 2), 256>>>(xc + 32, XC_STRIDE, 2);
  gathermax_kernel<128><<<NROWS/8, 256>>>(xc + 96);

  // ---- global conv + maxpool + heads ----
  globalconv_kernel<<<dim3(NPTS/64, BATCH, 4), 256>>>(xc);
  head_kernel<<<1, 256>>>(Wv1, bv1, Wv2, bv2, Wq1, bq1, Wq2, bq2, out);
}